// round 16
// baseline (speedup 1.0000x reference)
#include <cuda_runtime.h>
#include <cuda_bf16.h>
#include <math.h>

#define BATCH    512
#define FDIM     128
#define KNEG     4096
#define NDATA    1200000
#define INV_TEMP (1.0f/0.07f)
#define EPSN     1e-12f
#define SLOTS    16
#define SPILL_CAP 8192

#define FUSED_BLOCKS 1184   // 148 SMs x 8 blocks: exactly one wave at occ 8

// scratch (device globals; no runtime allocation allowed)
__device__ float          g_s[BATCH * FDIM];
__device__ __nv_bfloat16  g_sb[BATCH * FDIM];
__device__ float          g_t[BATCH * FDIM];
__device__ float          g_pos[BATCH];
__device__ float          g_sumexp[BATCH];          // sum exp(logit - M), M = 1/TEMP
__device__ unsigned int   g_count[NDATA];
__device__ unsigned short g_table[(size_t)NDATA * SLOTS];
__device__ unsigned int   g_spill[SPILL_CAP];
__device__ unsigned int   g_nspill;

__device__ __forceinline__ float warpSum(float v) {
#pragma unroll
    for (int o = 16; o > 0; o >>= 1) v += __shfl_xor_sync(0xffffffffu, v, o);
    return v;
}

__device__ __forceinline__ float blockSum128(float v, float* sh) {
    int w = threadIdx.x >> 5, l = threadIdx.x & 31;
    v = warpSum(v);
    if (l == 0) sh[w] = v;
    __syncthreads();
    float t = sh[0] + sh[1] + sh[2] + sh[3];
    __syncthreads();
    return t;
}

// ---------------------------------------------------------------------------
// 1) normalize s/t + pos logits + CLEAR g_count (grid-stride, fused in)
__global__ void prep_kernel(const float* __restrict__ stu,
                            const float* __restrict__ tea) {
    __shared__ float sh[4];
    int b = blockIdx.x, d = threadIdx.x;

    {
        unsigned gid = b * 128 + d;
        uint4 z = make_uint4(0, 0, 0, 0);
        for (unsigned i = gid; i < NDATA / 4; i += BATCH * 128)
            reinterpret_cast<uint4*>(g_count)[i] = z;
        if (gid == 0) g_nspill = 0;
    }

    float sv = stu[b * FDIM + d];
    float tv = tea[b * FDIM + d];
    float sn2 = blockSum128(sv * sv, sh);
    float tn2 = blockSum128(tv * tv, sh);
    float sn = sv / fmaxf(sqrtf(sn2), EPSN);
    float tn = tv / fmaxf(sqrtf(tn2), EPSN);
    g_s[b * FDIM + d] = sn;
    g_sb[b * FDIM + d] = __float2bfloat16(sn);
    g_t[b * FDIM + d] = tn;
    float pos = blockSum128(sn * tn, sh) * INV_TEMP;
    if (d == 0) {
        g_pos[b] = pos;
        g_sumexp[b] = __expf(pos - INV_TEMP);
    }
}

// ---------------------------------------------------------------------------
// 2) build inverted index: 2 r-entries per thread (uint2, same batch row)
__global__ void build_kernel(const int* __restrict__ r,
                             const int* __restrict__ idxs) {
    int gid = blockIdx.x * blockDim.x + threadIdx.x;   // BATCH*KNEG/2 threads
    int b = gid >> 11;                                 // 2048 pairs per row
    int2 rv = __ldg(reinterpret_cast<const int2*>(r) + gid);
    int self = __ldg(&idxs[b]);
#pragma unroll
    for (int e = 0; e < 2; e++) {
        int rve = (e == 0) ? rv.x : rv.y;
        int n = rve + (rve >= self);
        unsigned c = atomicAdd(&g_count[n], 1u);
        if (c < SLOTS) {
            g_table[(size_t)n * SLOTS + c] = (unsigned short)b;
        } else {
            unsigned p = atomicAdd(&g_nspill, 1u);
            if (p < SPILL_CAP) g_spill[p] = ((unsigned)n << 9) | (unsigned)b;
        }
    }
}

// ---------------------------------------------------------------------------
__device__ __forceinline__ float dotPart(float4 vk, int b, int lane) {
    uint2 sw = *reinterpret_cast<const uint2*>(&g_sb[b * FDIM + 4 * lane]);
    float2 f01 = __bfloat1622float2(*reinterpret_cast<__nv_bfloat162*>(&sw.x));
    float2 f23 = __bfloat1622float2(*reinterpret_cast<__nv_bfloat162*>(&sw.y));
    return fmaf(vk.x, f01.x, fmaf(vk.y, f01.y, fmaf(vk.z, f23.x, vk.w * f23.y)));
}

#define RED1(a)          { _Pragma("unroll") for (int o = 16; o > 0; o >>= 1) { a += __shfl_xor_sync(0xffffffffu, a, o); } }
#define RED2(a,b)        { _Pragma("unroll") for (int o = 16; o > 0; o >>= 1) { a += __shfl_xor_sync(0xffffffffu, a, o); b += __shfl_xor_sync(0xffffffffu, b, o); } }
#define RED3(a,b,c)      { _Pragma("unroll") for (int o = 16; o > 0; o >>= 1) { a += __shfl_xor_sync(0xffffffffu, a, o); b += __shfl_xor_sync(0xffffffffu, b, o); c += __shfl_xor_sync(0xffffffffu, c, o); } }
#define RED4(a,b,c,d)    { _Pragma("unroll") for (int o = 16; o > 0; o >>= 1) { a += __shfl_xor_sync(0xffffffffu, a, o); b += __shfl_xor_sync(0xffffffffu, b, o); c += __shfl_xor_sync(0xffffffffu, c, o); d += __shfl_xor_sync(0xffffffffu, d, o); } }

// ---------------------------------------------------------------------------
// FUSED single pass over the bank (R9 loop body, occupancy 8 experiment):
//   - shifted copy via ONE rotate-shuffle per row -> aligned STG.128
//   - dedup'd negative dots, m-specialized reduction trees
// Rows are unit-norm by construction -> no re-normalization.
__global__ __launch_bounds__(256, 8)
void fused_kernel(const float* __restrict__ bank, float* __restrict__ out) {
    __shared__ float ssum[BATCH];
    for (int t = threadIdx.x; t < BATCH; t += 256) ssum[t] = 0.0f;
    __syncthreads();

    const long long NTOT = (long long)NDATA * FDIM;    // 153,600,000
    int lane = threadIdx.x & 31;
    int gw = (blockIdx.x * blockDim.x + threadIdx.x) >> 5;
    int nwarps = FUSED_BLOCKS * 8;
    const int NCHUNK = NDATA / 4;                      // 300,000
    int srcLane = (lane + 31) & 31;

    if (gw == 0 && lane == 0) {                        // global edges
        out[1] = bank[0];
        out[2] = bank[1];
        out[3] = bank[2];
        out[NTOT] = bank[NTOT - 1];
    }

    for (int ch = gw; ch < NCHUNK; ch += nwarps) {
        long long f0 = (long long)ch * 512;
        int n0 = ch * 4;

        // ---- all long-latency loads issued up front (MLP >= 6) ----
        uint4 c4 = __ldg(reinterpret_cast<const uint4*>(&g_count[n0]));
        float4 v[4];
#pragma unroll
        for (int k = 0; k < 4; k++)
            v[k] = __ldcs(reinterpret_cast<const float4*>(bank + f0 + k * FDIM) + lane);
        float prevlast = 0.0f;                          // src[f0-1], broadcast
        if (ch > 0) prevlast = __ldg(&bank[f0 - 1]);

        // ---- shifted copy: ONE rotate shuffle per row ----
#pragma unroll
        for (int k = 0; k < 4; k++) {
            float srcv = v[k].w;
            if (lane == 31) srcv = (k == 0) ? prevlast : v[k - 1].w;
            float pw = __shfl_sync(0xffffffffu, srcv, srcLane);
            long long j = f0 + k * FDIM + 4 * lane;
            if (j > 0)                                   // j==0 would hit out[0]=loss
                *reinterpret_cast<float4*>(out + j) =
                    make_float4(pw, v[k].x, v[k].y, v[k].z);
        }

        // ---- dedup'd negative dots ----
        unsigned cnts[4] = { c4.x, c4.y, c4.z, c4.w };
#pragma unroll
        for (int k = 0; k < 4; k++) {
            unsigned cc = cnts[k];
            if (cc == 0) continue;
            if (cc > SLOTS) cc = SLOTS;
            int n = n0 + k;
            float4 vk = v[k];
            unsigned tb = (lane < (int)cc)
                          ? (unsigned)g_table[(size_t)n * SLOTS + lane] : 0u;
            for (unsigned j0 = 0; j0 < cc; j0 += 4) {
                unsigned m = cc - j0; if (m > 4) m = 4;
                float d0 = 0.f, d1 = 0.f, d2 = 0.f, d3 = 0.f;
                {
                    int b = __shfl_sync(0xffffffffu, tb, j0 + 0);
                    d0 = dotPart(vk, b, lane);
                }
                if (m > 1) {
                    int b = __shfl_sync(0xffffffffu, tb, j0 + 1);
                    d1 = dotPart(vk, b, lane);
                }
                if (m > 2) {
                    int b = __shfl_sync(0xffffffffu, tb, j0 + 2);
                    d2 = dotPart(vk, b, lane);
                }
                if (m > 3) {
                    int b = __shfl_sync(0xffffffffu, tb, j0 + 3);
                    d3 = dotPart(vk, b, lane);
                }
                switch (m) {
                    case 1: RED1(d0);              break;
                    case 2: RED2(d0, d1);          break;
                    case 3: RED3(d0, d1, d2);      break;
                    default: RED4(d0, d1, d2, d3); break;
                }
                int bb = __shfl_sync(0xffffffffu, tb, j0 + lane);
                if (lane < (int)m) {
                    float dd = (lane == 0) ? d0 : (lane == 1) ? d1 : (lane == 2) ? d2 : d3;
                    atomicAdd(&ssum[bb], __expf(fmaf(dd, INV_TEMP, -INV_TEMP)));
                }
            }
        }
    }

    __syncthreads();
    for (int t = threadIdx.x; t < BATCH; t += 256) {
        float s = ssum[t];
        if (s != 0.0f) atomicAdd(&g_sumexp[t], s);
    }
}

// ---------------------------------------------------------------------------
// epilogue: blocks 0..31 scatter (warp-per-row), block 32 spill+loss.
// outBank = out + 1 is 4B-misaligned for float4 -> scalar stores (coalesced).
__global__ __launch_bounds__(512)
void epilogue_kernel(const float* __restrict__ bank,
                     const int* __restrict__ idxs,
                     float* __restrict__ out) {
    int tid = threadIdx.x;
    int lane = tid & 31;

    if (blockIdx.x < 32) {
        // ---------------- scatter ----------------
        float* outBank = out + 1;
        int b = blockIdx.x * 16 + (tid >> 5);          // 32 blocks x 16 warps
        int idx = __ldg(&idxs[b]);

        float4 bv = __ldg(reinterpret_cast<const float4*>(bank + (size_t)idx * FDIM) + lane);
        float4 tv = *reinterpret_cast<const float4*>(&g_t[b * FDIM + 4 * lane]);

        bool dup = false;
        for (int bb = b + 1 + lane; bb < BATCH; bb += 32)
            dup |= (__ldg(&idxs[bb]) == idx);
        unsigned dm = __ballot_sync(0xffffffffu, dup);

        float4 u;
        u.x = 0.5f * bv.x + 0.5f * tv.x;
        u.y = 0.5f * bv.y + 0.5f * tv.y;
        u.z = 0.5f * bv.z + 0.5f * tv.z;
        u.w = 0.5f * bv.w + 0.5f * tv.w;
        float n2 = warpSum(fmaf(u.x, u.x, fmaf(u.y, u.y, fmaf(u.z, u.z, u.w * u.w))));
        float inv = 1.0f / fmaxf(sqrtf(n2), EPSN);
        if (dm == 0) {
            float* op = outBank + (size_t)idx * FDIM + 4 * lane;   // 4B-aligned only
            op[0] = u.x * inv;
            op[1] = u.y * inv;
            op[2] = u.z * inv;
            op[3] = u.w * inv;
        }
        return;
    }

    // ---------------- spill + loss (block 32) ----------------
    __shared__ float sh[16];
    int warp = tid >> 5;

    unsigned ns = g_nspill;
    if (ns > SPILL_CAP) ns = SPILL_CAP;
    for (unsigned e = warp; e < ns; e += 16) {
        unsigned p = g_spill[e];
        int n = p >> 9, b = p & 511;
        float4 v = *(reinterpret_cast<const float4*>(bank + (size_t)n * FDIM) + lane);
        float4 s4 = *reinterpret_cast<const float4*>(&g_s[b * FDIM + 4 * lane]);
        float d = warpSum(fmaf(v.x, s4.x, fmaf(v.y, s4.y, fmaf(v.z, s4.z, v.w * s4.w))));
        if (lane == 0) atomicAdd(&g_sumexp[b], __expf(d * INV_TEMP - INV_TEMP));
    }
    __syncthreads();

    float v = INV_TEMP + logf(g_sumexp[tid]) - g_pos[tid];
    v = warpSum(v);
    if (lane == 0) sh[warp] = v;
    __syncthreads();
    if (tid == 0) {
        float tot = 0.0f;
#pragma unroll
        for (int w = 0; w < 16; w++) tot += sh[w];
        out[0] = tot * (1.0f / BATCH);
    }
}

// ---------------------------------------------------------------------------
extern "C" void kernel_launch(void* const* d_in, const int* in_sizes, int n_in,
                              void* d_out, int out_size) {
    const float* stu  = (const float*)d_in[0];
    const float* tea  = (const float*)d_in[1];
    const float* bank = (const float*)d_in[2];
    const int*   idxs = (const int*)d_in[3];
    const int*   r    = (const int*)d_in[4];
    float* out = (float*)d_out;

    prep_kernel<<<BATCH, 128>>>(stu, tea);            // also clears g_count
    build_kernel<<<(BATCH * KNEG / 2) / 256, 256>>>(r, idxs);
    fused_kernel<<<FUSED_BLOCKS, 256>>>(bank, out);
    epilogue_kernel<<<33, 512>>>(bank, idxs, out);
}

// round 17
// speedup vs baseline: 1.1035x; 1.1035x over previous
#include <cuda_runtime.h>
#include <cuda_bf16.h>
#include <math.h>

#define BATCH    512
#define FDIM     128
#define KNEG     4096
#define NDATA    1200000
#define INV_TEMP (1.0f/0.07f)
#define EPSN     1e-12f
#define SLOTS    16
#define SPILL_CAP 8192

#define FUSED_BLOCKS 888    // 148 SMs x 6 blocks (proven best occupancy point)

// scratch (device globals; no runtime allocation allowed)
__device__ float          g_s[BATCH * FDIM];
__device__ __nv_bfloat16  g_sb[BATCH * FDIM];
__device__ float          g_t[BATCH * FDIM];
__device__ float          g_pos[BATCH];
__device__ float          g_sumexp[BATCH];          // sum exp(logit - M), M = 1/TEMP
__device__ unsigned int   g_count[NDATA];
__device__ unsigned short g_table[(size_t)NDATA * SLOTS];
__device__ unsigned int   g_spill[SPILL_CAP];
__device__ unsigned int   g_nspill;

__device__ __forceinline__ float warpSum(float v) {
#pragma unroll
    for (int o = 16; o > 0; o >>= 1) v += __shfl_xor_sync(0xffffffffu, v, o);
    return v;
}

__device__ __forceinline__ float blockSum128(float v, float* sh) {
    int w = threadIdx.x >> 5, l = threadIdx.x & 31;
    v = warpSum(v);
    if (l == 0) sh[w] = v;
    __syncthreads();
    float t = sh[0] + sh[1] + sh[2] + sh[3];
    __syncthreads();
    return t;
}

// ---------------------------------------------------------------------------
// 1) normalize s/t + pos logits + CLEAR g_count (grid-stride, fused in)
__global__ void prep_kernel(const float* __restrict__ stu,
                            const float* __restrict__ tea) {
    __shared__ float sh[4];
    int b = blockIdx.x, d = threadIdx.x;

    {
        unsigned gid = b * 128 + d;
        uint4 z = make_uint4(0, 0, 0, 0);
        for (unsigned i = gid; i < NDATA / 4; i += BATCH * 128)
            reinterpret_cast<uint4*>(g_count)[i] = z;
        if (gid == 0) g_nspill = 0;
    }

    float sv = stu[b * FDIM + d];
    float tv = tea[b * FDIM + d];
    float sn2 = blockSum128(sv * sv, sh);
    float tn2 = blockSum128(tv * tv, sh);
    float sn = sv / fmaxf(sqrtf(sn2), EPSN);
    float tn = tv / fmaxf(sqrtf(tn2), EPSN);
    g_s[b * FDIM + d] = sn;
    g_sb[b * FDIM + d] = __float2bfloat16(sn);
    g_t[b * FDIM + d] = tn;
    float pos = blockSum128(sn * tn, sh) * INV_TEMP;
    if (d == 0) {
        g_pos[b] = pos;
        g_sumexp[b] = __expf(pos - INV_TEMP);
    }
}

// ---------------------------------------------------------------------------
// 2) build inverted index: 2 r-entries per thread (uint2, same batch row)
__global__ void build_kernel(const int* __restrict__ r,
                             const int* __restrict__ idxs) {
    int gid = blockIdx.x * blockDim.x + threadIdx.x;   // BATCH*KNEG/2 threads
    int b = gid >> 11;                                 // 2048 pairs per row
    int2 rv = __ldg(reinterpret_cast<const int2*>(r) + gid);
    int self = __ldg(&idxs[b]);
#pragma unroll
    for (int e = 0; e < 2; e++) {
        int rve = (e == 0) ? rv.x : rv.y;
        int n = rve + (rve >= self);
        unsigned c = atomicAdd(&g_count[n], 1u);
        if (c < SLOTS) {
            g_table[(size_t)n * SLOTS + c] = (unsigned short)b;
        } else {
            unsigned p = atomicAdd(&g_nspill, 1u);
            if (p < SPILL_CAP) g_spill[p] = ((unsigned)n << 9) | (unsigned)b;
        }
    }
}

// ---------------------------------------------------------------------------
__device__ __forceinline__ float dotPart(float4 vk, int b, int lane) {
    uint2 sw = *reinterpret_cast<const uint2*>(&g_sb[b * FDIM + 4 * lane]);
    float2 f01 = __bfloat1622float2(*reinterpret_cast<__nv_bfloat162*>(&sw.x));
    float2 f23 = __bfloat1622float2(*reinterpret_cast<__nv_bfloat162*>(&sw.y));
    return fmaf(vk.x, f01.x, fmaf(vk.y, f01.y, fmaf(vk.z, f23.x, vk.w * f23.y)));
}

#define RED1(a)          { _Pragma("unroll") for (int o = 16; o > 0; o >>= 1) { a += __shfl_xor_sync(0xffffffffu, a, o); } }
#define RED2(a,b)        { _Pragma("unroll") for (int o = 16; o > 0; o >>= 1) { a += __shfl_xor_sync(0xffffffffu, a, o); b += __shfl_xor_sync(0xffffffffu, b, o); } }
#define RED3(a,b,c)      { _Pragma("unroll") for (int o = 16; o > 0; o >>= 1) { a += __shfl_xor_sync(0xffffffffu, a, o); b += __shfl_xor_sync(0xffffffffu, b, o); c += __shfl_xor_sync(0xffffffffu, c, o); } }
#define RED4(a,b,c,d)    { _Pragma("unroll") for (int o = 16; o > 0; o >>= 1) { a += __shfl_xor_sync(0xffffffffu, a, o); b += __shfl_xor_sync(0xffffffffu, b, o); c += __shfl_xor_sync(0xffffffffu, c, o); d += __shfl_xor_sync(0xffffffffu, d, o); } }

// ---------------------------------------------------------------------------
// FUSED single pass over the bank (R9 loop body + up-front table loads):
//   - shifted copy via ONE rotate-shuffle per row -> aligned STG.128
//   - dedup'd negative dots; ALL table slots for the 4 rows are fetched by
//     2 coalesced LDG.U16 issued WITH the row loads (64 contiguous shorts),
//     so the dot section contains no global loads except L1-resident g_sb.
// Rows are unit-norm by construction -> no re-normalization.
__global__ __launch_bounds__(256, 6)
void fused_kernel(const float* __restrict__ bank, float* __restrict__ out) {
    __shared__ float ssum[BATCH];
    for (int t = threadIdx.x; t < BATCH; t += 256) ssum[t] = 0.0f;
    __syncthreads();

    const long long NTOT = (long long)NDATA * FDIM;    // 153,600,000
    int lane = threadIdx.x & 31;
    int gw = (blockIdx.x * blockDim.x + threadIdx.x) >> 5;
    int nwarps = FUSED_BLOCKS * 8;
    const int NCHUNK = NDATA / 4;                      // 300,000
    int srcLane = (lane + 31) & 31;

    if (gw == 0 && lane == 0) {                        // global edges
        out[1] = bank[0];
        out[2] = bank[1];
        out[3] = bank[2];
        out[NTOT] = bank[NTOT - 1];
    }

    for (int ch = gw; ch < NCHUNK; ch += nwarps) {
        long long f0 = (long long)ch * 512;
        int n0 = ch * 4;

        // ---- all long-latency loads issued up front (MLP >= 8) ----
        uint4 c4 = __ldg(reinterpret_cast<const uint4*>(&g_count[n0]));
        float4 v[4];
#pragma unroll
        for (int k = 0; k < 4; k++)
            v[k] = __ldcs(reinterpret_cast<const float4*>(bank + f0 + k * FDIM) + lane);
        // table slots for all 4 rows: 64 contiguous shorts, 2 warp loads.
        // Unconditional; garbage beyond cc is never consumed (j < cc guards).
        unsigned tbA = (unsigned)__ldg(&g_table[(size_t)n0 * SLOTS + lane]);       // rows 0,1
        unsigned tbB = (unsigned)__ldg(&g_table[(size_t)n0 * SLOTS + 32 + lane]);  // rows 2,3
        float prevlast = 0.0f;                          // src[f0-1], broadcast
        if (ch > 0) prevlast = __ldg(&bank[f0 - 1]);

        // ---- shifted copy: ONE rotate shuffle per row ----
#pragma unroll
        for (int k = 0; k < 4; k++) {
            float srcv = v[k].w;
            if (lane == 31) srcv = (k == 0) ? prevlast : v[k - 1].w;
            float pw = __shfl_sync(0xffffffffu, srcv, srcLane);
            long long j = f0 + k * FDIM + 4 * lane;
            if (j > 0)                                   // j==0 would hit out[0]=loss
                *reinterpret_cast<float4*>(out + j) =
                    make_float4(pw, v[k].x, v[k].y, v[k].z);
        }

        // ---- dedup'd negative dots (no loads besides L1-resident g_sb) ----
        unsigned cnts[4] = { c4.x, c4.y, c4.z, c4.w };
#pragma unroll
        for (int k = 0; k < 4; k++) {
            unsigned cc = cnts[k];
            if (cc == 0) continue;
            if (cc > SLOTS) cc = SLOTS;
            float4 vk = v[k];
            unsigned tbk = (k < 2) ? tbA : tbB;
            int base = (k & 1) * 16;                    // slot j of row k at lane base+j
            for (unsigned j0 = 0; j0 < cc; j0 += 4) {
                unsigned m = cc - j0; if (m > 4) m = 4;
                float d0 = 0.f, d1 = 0.f, d2 = 0.f, d3 = 0.f;
                {
                    int b = __shfl_sync(0xffffffffu, tbk, base + j0 + 0);
                    d0 = dotPart(vk, b, lane);
                }
                if (m > 1) {
                    int b = __shfl_sync(0xffffffffu, tbk, base + j0 + 1);
                    d1 = dotPart(vk, b, lane);
                }
                if (m > 2) {
                    int b = __shfl_sync(0xffffffffu, tbk, base + j0 + 2);
                    d2 = dotPart(vk, b, lane);
                }
                if (m > 3) {
                    int b = __shfl_sync(0xffffffffu, tbk, base + j0 + 3);
                    d3 = dotPart(vk, b, lane);
                }
                switch (m) {
                    case 1: RED1(d0);              break;
                    case 2: RED2(d0, d1);          break;
                    case 3: RED3(d0, d1, d2);      break;
                    default: RED4(d0, d1, d2, d3); break;
                }
                int bb = __shfl_sync(0xffffffffu, tbk, base + j0 + lane);
                if (lane < (int)m) {
                    float dd = (lane == 0) ? d0 : (lane == 1) ? d1 : (lane == 2) ? d2 : d3;
                    atomicAdd(&ssum[bb], __expf(fmaf(dd, INV_TEMP, -INV_TEMP)));
                }
            }
        }
    }

    __syncthreads();
    for (int t = threadIdx.x; t < BATCH; t += 256) {
        float s = ssum[t];
        if (s != 0.0f) atomicAdd(&g_sumexp[t], s);
    }
}

// ---------------------------------------------------------------------------
// epilogue: blocks 0..31 scatter (warp-per-row), block 32 spill+loss.
// outBank = out + 1 is 4B-misaligned for float4 -> scalar stores (coalesced).
__global__ __launch_bounds__(512)
void epilogue_kernel(const float* __restrict__ bank,
                     const int* __restrict__ idxs,
                     float* __restrict__ out) {
    int tid = threadIdx.x;
    int lane = tid & 31;

    if (blockIdx.x < 32) {
        // ---------------- scatter ----------------
        float* outBank = out + 1;
        int b = blockIdx.x * 16 + (tid >> 5);          // 32 blocks x 16 warps
        int idx = __ldg(&idxs[b]);

        float4 bv = __ldg(reinterpret_cast<const float4*>(bank + (size_t)idx * FDIM) + lane);
        float4 tv = *reinterpret_cast<const float4*>(&g_t[b * FDIM + 4 * lane]);

        bool dup = false;
        for (int bb = b + 1 + lane; bb < BATCH; bb += 32)
            dup |= (__ldg(&idxs[bb]) == idx);
        unsigned dm = __ballot_sync(0xffffffffu, dup);

        float4 u;
        u.x = 0.5f * bv.x + 0.5f * tv.x;
        u.y = 0.5f * bv.y + 0.5f * tv.y;
        u.z = 0.5f * bv.z + 0.5f * tv.z;
        u.w = 0.5f * bv.w + 0.5f * tv.w;
        float n2 = warpSum(fmaf(u.x, u.x, fmaf(u.y, u.y, fmaf(u.z, u.z, u.w * u.w))));
        float inv = 1.0f / fmaxf(sqrtf(n2), EPSN);
        if (dm == 0) {
            float* op = outBank + (size_t)idx * FDIM + 4 * lane;   // 4B-aligned only
            op[0] = u.x * inv;
            op[1] = u.y * inv;
            op[2] = u.z * inv;
            op[3] = u.w * inv;
        }
        return;
    }

    // ---------------- spill + loss (block 32) ----------------
    __shared__ float sh[16];
    int warp = tid >> 5;

    unsigned ns = g_nspill;
    if (ns > SPILL_CAP) ns = SPILL_CAP;
    for (unsigned e = warp; e < ns; e += 16) {
        unsigned p = g_spill[e];
        int n = p >> 9, b = p & 511;
        float4 v = *(reinterpret_cast<const float4*>(bank + (size_t)n * FDIM) + lane);
        float4 s4 = *reinterpret_cast<const float4*>(&g_s[b * FDIM + 4 * lane]);
        float d = warpSum(fmaf(v.x, s4.x, fmaf(v.y, s4.y, fmaf(v.z, s4.z, v.w * s4.w))));
        if (lane == 0) atomicAdd(&g_sumexp[b], __expf(d * INV_TEMP - INV_TEMP));
    }
    __syncthreads();

    float v = INV_TEMP + logf(g_sumexp[tid]) - g_pos[tid];
    v = warpSum(v);
    if (lane == 0) sh[warp] = v;
    __syncthreads();
    if (tid == 0) {
        float tot = 0.0f;
#pragma unroll
        for (int w = 0; w < 16; w++) tot += sh[w];
        out[0] = tot * (1.0f / BATCH);
    }
}

// ---------------------------------------------------------------------------
extern "C" void kernel_launch(void* const* d_in, const int* in_sizes, int n_in,
                              void* d_out, int out_size) {
    const float* stu  = (const float*)d_in[0];
    const float* tea  = (const float*)d_in[1];
    const float* bank = (const float*)d_in[2];
    const int*   idxs = (const int*)d_in[3];
    const int*   r    = (const int*)d_in[4];
    float* out = (float*)d_out;

    prep_kernel<<<BATCH, 128>>>(stu, tea);            // also clears g_count
    build_kernel<<<(BATCH * KNEG / 2) / 256, 256>>>(r, idxs);
    fused_kernel<<<FUSED_BLOCKS, 256>>>(bank, out);
    epilogue_kernel<<<33, 512>>>(bank, idxs, out);
}